// round 5
// baseline (speedup 1.0000x reference)
#include <cuda_runtime.h>
#include <math.h>

// Problem shape (fixed by the dataset): B=8, T=4096, D=64
constexpr int B = 8;
constexpr int T = 4096;
constexpr int D = 64;

// -------- device scratch (no allocations allowed) --------
__device__ float g_Xsel[B][T][D];   // normalized, compacted selected rows of x
__device__ float g_Ysel[B][T][D];   // normalized, compacted selected rows of y
__device__ int   g_rsel[B][T];
__device__ int   g_csel[B][T];
__device__ int   g_nx[B];
__device__ int   g_ny[B];
__device__ float g_percol[B][T];    // per-column LSE (fixed-shift), j < m
__device__ float g_batchloss[B];

// -------- packed f32x2 helpers (FFMA2: 2 MACs per issue slot) --------
__device__ __forceinline__ void fma2(unsigned long long& d,
                                     unsigned long long a,
                                     unsigned long long b) {
    asm("fma.rn.f32x2 %0, %1, %2, %0;" : "+l"(d) : "l"(a), "l"(b));
}
__device__ __forceinline__ void add2(unsigned long long& d,
                                     unsigned long long a,
                                     unsigned long long b) {
    asm("add.rn.f32x2 %0, %1, %2;" : "=l"(d) : "l"(a), "l"(b));
}
__device__ __forceinline__ unsigned long long pack2(float lo, float hi) {
    unsigned long long r;
    asm("mov.b64 %0, {%1, %2};" : "=l"(r) : "f"(lo), "f"(hi));
    return r;
}
__device__ __forceinline__ void unpack2(float& lo, float& hi, unsigned long long a) {
    asm("mov.b64 {%0, %1}, %2;" : "=f"(lo), "=f"(hi) : "l"(a));
}

// ============================================================
// Kernel 1: stable compaction of selected indices (per batch)
// ============================================================
__global__ void compact_kernel(const int* __restrict__ im1, const int* __restrict__ im2,
                               const int* __restrict__ sh1, const int* __restrict__ sh2) {
    int b   = blockIdx.x;
    int tid = threadIdx.x;
    int lane = tid & 31, wid = tid >> 5;
    __shared__ int wtot[32];

    for (int sel = 0; sel < 2; ++sel) {
        const int* im = sel ? im2 : im1;
        const int* sh = sel ? sh2 : sh1;
        int* outp = sel ? &g_csel[b][0] : &g_rsel[b][0];

        int t0 = tid * 4;
        int v[4];
        int cnt = 0;
        #pragma unroll
        for (int i = 0; i < 4; ++i) {
            int t = t0 + i;
            v[i] = (im[b * T + t] != 0 && sh[b * T + t] != 0) ? 1 : 0;
            cnt += v[i];
        }
        int incl = cnt;
        #pragma unroll
        for (int o = 1; o < 32; o <<= 1) {
            int tt = __shfl_up_sync(0xffffffffu, incl, o);
            if (lane >= o) incl += tt;
        }
        if (lane == 31) wtot[wid] = incl;
        __syncthreads();
        if (wid == 0) {
            int val  = wtot[lane];
            int winc = val;
            #pragma unroll
            for (int o = 1; o < 32; o <<= 1) {
                int tt = __shfl_up_sync(0xffffffffu, winc, o);
                if (lane >= o) winc += tt;
            }
            wtot[lane] = winc - val;
            if (lane == 31) {
                if (sel) g_ny[b] = winc; else g_nx[b] = winc;
            }
        }
        __syncthreads();
        int off = wtot[wid] + (incl - cnt);
        #pragma unroll
        for (int i = 0; i < 4; ++i)
            if (v[i]) outp[off++] = t0 + i;
        __syncthreads();
    }
}

// ============================================================
// Kernel 2: gather selected rows + L2-normalize
// ============================================================
__global__ void gather_norm_kernel(const float* __restrict__ x, const float* __restrict__ y) {
    int b     = blockIdx.y;
    int which = blockIdx.z;
    int wid  = threadIdx.x >> 5;
    int lane = threadIdx.x & 31;
    int p = blockIdx.x * 8 + wid;

    int count = which ? g_ny[b] : g_nx[b];
    if (p >= count) return;
    int r = which ? g_csel[b][p] : g_rsel[b][p];

    const float* src = (which ? y : x) + ((size_t)b * T + r) * D;
    float2 v = reinterpret_cast<const float2*>(src)[lane];
    float ss = v.x * v.x + v.y * v.y;
    #pragma unroll
    for (int o = 16; o > 0; o >>= 1) ss += __shfl_xor_sync(0xffffffffu, ss, o);
    float n  = sqrtf(ss);
    float sc = 1.0f / fmaxf(n, 1e-12f);

    float* dst = which ? &g_Ysel[b][p][0] : &g_Xsel[b][p][0];
    reinterpret_cast<float2*>(dst)[lane] = make_float2(v.x * sc, v.y * sc);
}

// ============================================================
// Kernel 3: fused GEMM + fixed-shift column-LSE
// grid: (T/64, B), block 128 (4 warps).
// Lane owns 2 columns: c0 = colbase+lane, c1 = colbase+32+lane.
// Y packed per-k as (y_c0[k], y_c1[k]) in 64 u64 regs.
// X tile staged DUPLICATED in smem: (x_k, x_k) pairs -> every
// fma.rn.f32x2 is 2 useful MACs (one per column), no hsum needed.
// Logits <= 10 (normalized dots) -> LSE with fixed shift 10, no max,
// no branches: S += expf(10*dot - 10), lse = 10 + log(S).
// ============================================================
__global__ void __launch_bounds__(128, 2)
simloss_kernel() {
    int b  = blockIdx.y;
    int nx = g_nx[b];
    int ny = g_ny[b];
    int m  = min(nx, ny);
    int colbase = blockIdx.x * 64;
    if (colbase >= m) return;

    int tid  = threadIdx.x;
    int lane = tid & 31;
    int rl   = tid >> 5;               // warp id 0..3
    int c0   = colbase + lane;
    int c1   = colbase + 32 + lane;    // always < T; rows >= ny are zeros (BSS, never written)

    // y pair columns packed: y2[k] = (Y[c0][k], Y[c1][k])
    unsigned long long y2[D];
    {
        const float2* y0 = reinterpret_cast<const float2*>(&g_Ysel[b][c0][0]);
        const float2* y1 = reinterpret_cast<const float2*>(&g_Ysel[b][c1][0]);
        #pragma unroll
        for (int k = 0; k < 32; ++k) {
            float2 a = y0[k];
            float2 bb = y1[k];
            y2[2 * k]     = pack2(a.x, bb.x);
            y2[2 * k + 1] = pack2(a.y, bb.y);
        }
    }

    __shared__ __align__(16) unsigned long long xdup[32 * D];  // 16 KB duplicated tile
    __shared__ float redS[4][64];

    float S0 = 0.0f, S1 = 0.0f;

    for (int rb = 0; rb < nx; rb += 32) {
        __syncthreads();
        // stage 32 rows duplicated: 512 float4 in -> 1024 float4 out, 128 threads
        {
            const float4* src = reinterpret_cast<const float4*>(&g_Xsel[b][rb][0]);
            float4*       dst = reinterpret_cast<float4*>(xdup);
            #pragma unroll
            for (int i = 0; i < 4; ++i) {
                int idx = tid + i * 128;          // 0..511
                float4 f = src[idx];
                int row = idx >> 4, kg = idx & 15;
                int o = row * 32 + kg * 2;
                dst[o]     = make_float4(f.x, f.x, f.y, f.y);
                dst[o + 1] = make_float4(f.z, f.z, f.w, f.w);
            }
        }
        __syncthreads();

        #pragma unroll 2
        for (int rr = 0; rr < 8; ++rr) {
            int rlocal = rl * 8 + rr;
            int grow   = rb + rlocal;
            if (grow >= nx) continue;             // warp-uniform
            const ulonglong2* xp = reinterpret_cast<const ulonglong2*>(&xdup[rlocal * D]);
            unsigned long long a0 = 0ull, a1 = 0ull;
            #pragma unroll
            for (int kk = 0; kk < 32; ++kk) {
                ulonglong2 t = xp[kk];            // broadcast LDS.128
                fma2(a0, t.x, y2[2 * kk]);
                fma2(a1, t.y, y2[2 * kk + 1]);
            }
            unsigned long long ap;
            add2(ap, a0, a1);
            float d0, d1;
            unpack2(d0, d1, ap);
            S0 += __expf(fmaf(d0, 10.0f, -10.0f));
            S1 += __expf(fmaf(d1, 10.0f, -10.0f));
        }
    }

    // merge 4 warps' partial sums per column
    redS[rl][lane]      = S0;
    redS[rl][lane + 32] = S1;
    __syncthreads();
    if (tid < 64) {
        int c = colbase + tid;
        if (c < m) {
            float S = redS[0][tid] + redS[1][tid] + redS[2][tid] + redS[3][tid];
            g_percol[b][c] = 10.0f + logf(S);     // lse with fixed shift
        }
    }
}

// ============================================================
// Kernel 4a: per-batch reduction (also recomputes diagonal dots)
// grid: B blocks x 1024 threads
// ============================================================
__global__ void reduce_batch_kernel() {
    int b   = blockIdx.x;
    int tid = threadIdx.x;
    int m   = min(g_nx[b], g_ny[b]);
    __shared__ float red[1024];

    float s = 0.0f;
    for (int j = tid; j < m; j += 1024) {
        const float4* xp = reinterpret_cast<const float4*>(&g_Xsel[b][j][0]);
        const float4* yp = reinterpret_cast<const float4*>(&g_Ysel[b][j][0]);
        float d = 0.0f;
        #pragma unroll
        for (int k = 0; k < 16; ++k) {
            float4 xv = xp[k], yv = yp[k];
            d += xv.x * yv.x + xv.y * yv.y + xv.z * yv.z + xv.w * yv.w;
        }
        s += g_percol[b][j] - 10.0f * d;          // lse - diag
    }
    red[tid] = s;
    __syncthreads();
    for (int st = 512; st > 0; st >>= 1) {
        if (tid < st) red[tid] += red[tid + st];
        __syncthreads();
    }
    if (tid == 0) g_batchloss[b] = (m > 0) ? red[0] / (float)m : 0.0f;
}

// ============================================================
// Kernel 4b: combine 8 batch losses -> scalar mean
// ============================================================
__global__ void combine_kernel(float* __restrict__ out) {
    if (threadIdx.x == 0) {
        float t = 0.0f;
        #pragma unroll
        for (int b = 0; b < B; ++b) t += g_batchloss[b];
        out[0] = t / (float)B;
    }
}

// ============================================================
extern "C" void kernel_launch(void* const* d_in, const int* in_sizes, int n_in,
                              void* d_out, int out_size) {
    const float* x   = (const float*)d_in[0];
    const float* y   = (const float*)d_in[1];
    const int*   im1 = (const int*)d_in[2];
    const int*   im2 = (const int*)d_in[3];
    const int*   sh1 = (const int*)d_in[4];
    const int*   sh2 = (const int*)d_in[5];

    compact_kernel<<<B, 1024>>>(im1, im2, sh1, sh2);
    gather_norm_kernel<<<dim3(T / 8, B, 2), 256>>>(x, y);
    simloss_kernel<<<dim3(T / 64, B), 128>>>();
    reduce_batch_kernel<<<B, 1024>>>();
    combine_kernel<<<1, 32>>>((float*)d_out);
}

// round 10
// speedup vs baseline: 3.5292x; 3.5292x over previous
#include <cuda_runtime.h>
#include <cuda_bf16.h>
#include <math.h>
#include <cstdint>

// Problem shape (fixed by the dataset): B=8, T=4096, D=64
constexpr int B = 8;
constexpr int T = 4096;
constexpr int D = 64;

// ---------------- device scratch (no allocations allowed) ----------------
__device__ __nv_bfloat16 g_Xb[B][T][D];   // normalized selected rows of x (bf16), zero-padded
__device__ __nv_bfloat16 g_Yb[B][T][D];   // normalized selected rows of y (bf16), zero-padded
__device__ int   g_rsel[B][T];
__device__ int   g_csel[B][T];
__device__ int   g_nx[B];
__device__ int   g_ny[B];
__device__ float g_percol[B][T];          // per-column fixed-shift LSE, j < m
__device__ float g_batchloss[B];

// ---------------- mma.sync / ldmatrix wrappers (plain sm_103 legal) -------
__device__ __forceinline__ uint32_t smem_u32(const void* p) {
    return (uint32_t)__cvta_generic_to_shared(p);
}
__device__ __forceinline__ void ldsm_x4(uint32_t addr, uint32_t r[4]) {
    asm volatile("ldmatrix.sync.aligned.m8n8.x4.shared.b16 {%0,%1,%2,%3}, [%4];"
                 : "=r"(r[0]), "=r"(r[1]), "=r"(r[2]), "=r"(r[3]) : "r"(addr));
}
__device__ __forceinline__ void ldsm_x4_trans(uint32_t addr, uint32_t r[4]) {
    asm volatile("ldmatrix.sync.aligned.m8n8.x4.trans.shared.b16 {%0,%1,%2,%3}, [%4];"
                 : "=r"(r[0]), "=r"(r[1]), "=r"(r[2]), "=r"(r[3]) : "r"(addr));
}
__device__ __forceinline__ void mma_bf16(float c[4], const uint32_t a[4],
                                         uint32_t b0, uint32_t b1) {
    asm volatile(
        "mma.sync.aligned.m16n8k16.row.col.f32.bf16.bf16.f32 "
        "{%0,%1,%2,%3}, {%4,%5,%6,%7}, {%8,%9}, {%0,%1,%2,%3};"
        : "+f"(c[0]), "+f"(c[1]), "+f"(c[2]), "+f"(c[3])
        : "r"(a[0]), "r"(a[1]), "r"(a[2]), "r"(a[3]), "r"(b0), "r"(b1));
}

// ============================================================
// Kernel 1: stable compaction of selected indices (per batch)
// ============================================================
__global__ void compact_kernel(const int* __restrict__ im1, const int* __restrict__ im2,
                               const int* __restrict__ sh1, const int* __restrict__ sh2) {
    int b   = blockIdx.x;
    int tid = threadIdx.x;
    int lane = tid & 31, wid = tid >> 5;
    __shared__ int wtot[32];

    for (int sel = 0; sel < 2; ++sel) {
        const int* im = sel ? im2 : im1;
        const int* sh = sel ? sh2 : sh1;
        int* outp = sel ? &g_csel[b][0] : &g_rsel[b][0];

        int t0 = tid * 4;
        int v[4];
        int cnt = 0;
        #pragma unroll
        for (int i = 0; i < 4; ++i) {
            int t = t0 + i;
            v[i] = (im[b * T + t] != 0 && sh[b * T + t] != 0) ? 1 : 0;
            cnt += v[i];
        }
        int incl = cnt;
        #pragma unroll
        for (int o = 1; o < 32; o <<= 1) {
            int tt = __shfl_up_sync(0xffffffffu, incl, o);
            if (lane >= o) incl += tt;
        }
        if (lane == 31) wtot[wid] = incl;
        __syncthreads();
        if (wid == 0) {
            int val  = wtot[lane];
            int winc = val;
            #pragma unroll
            for (int o = 1; o < 32; o <<= 1) {
                int tt = __shfl_up_sync(0xffffffffu, winc, o);
                if (lane >= o) winc += tt;
            }
            wtot[lane] = winc - val;
            if (lane == 31) {
                if (sel) g_ny[b] = winc; else g_nx[b] = winc;
            }
        }
        __syncthreads();
        int off = wtot[wid] + (incl - cnt);
        #pragma unroll
        for (int i = 0; i < 4; ++i)
            if (v[i]) outp[off++] = t0 + i;
        __syncthreads();
    }
}

// ============================================================
// Kernel 2: gather selected rows + L2-normalize -> bf16 tiles
// ============================================================
__global__ void gather_norm_kernel(const float* __restrict__ x, const float* __restrict__ y) {
    int b     = blockIdx.y;
    int which = blockIdx.z;
    int wid  = threadIdx.x >> 5;
    int lane = threadIdx.x & 31;
    int p = blockIdx.x * 8 + wid;

    int count = which ? g_ny[b] : g_nx[b];
    if (p >= count) return;
    int r = which ? g_csel[b][p] : g_rsel[b][p];

    const float* src = (which ? y : x) + ((size_t)b * T + r) * D;
    float2 v = reinterpret_cast<const float2*>(src)[lane];
    float ss = v.x * v.x + v.y * v.y;
    #pragma unroll
    for (int o = 16; o > 0; o >>= 1) ss += __shfl_xor_sync(0xffffffffu, ss, o);
    float sc = 1.0f / fmaxf(sqrtf(ss), 1e-12f);

    __nv_bfloat16* dst = which ? &g_Yb[b][p][0] : &g_Xb[b][p][0];
    reinterpret_cast<__nv_bfloat162*>(dst)[lane] =
        __floats2bfloat162_rn(v.x * sc, v.y * sc);
}

// ============================================================
// Kernel 3: HMMA (mma.sync bf16) GEMM + fixed-shift column exp-sums
// grid: (T/128, B), block 256 (8 warps).
// CTA owns 128 sim columns (Y rows colbase..+127); loops over 128-row
// X tiles; warp w owns the 16-row slab w of each tile.
// smem tiles use 144-byte row stride (9 x 16B) -> conflict-free ldmatrix.
// Zero-padded rows contribute exactly e^-10 per column -> subtracted.
// ============================================================
constexpr int TILE_ROWS  = 128;
constexpr int TILE_COLS  = 128;
constexpr int SROW_BYTES = 144;          // 64 bf16 = 128B data + 16B pad

__device__ __forceinline__ void stage_tile(char* dst, const __nv_bfloat16* src, int tid) {
    // 128 rows x 8 chunks of 16B, 256 threads -> 4 iterations, coalesced loads
    #pragma unroll
    for (int i = 0; i < 4; ++i) {
        int g = i * 256 + tid;
        int row = g >> 3, chunk = g & 7;
        uint4 v = *reinterpret_cast<const uint4*>(src + row * D + chunk * 8);
        *reinterpret_cast<uint4*>(dst + row * SROW_BYTES + chunk * 16) = v;
    }
}

__global__ void __launch_bounds__(256)
simloss_mma_kernel() {
    int b  = blockIdx.y;
    int nx = g_nx[b];
    int ny = g_ny[b];
    int m  = min(nx, ny);
    int colbase = blockIdx.x * TILE_COLS;
    if (colbase >= m) return;
    (void)ny;

    int tid  = threadIdx.x;
    int lane = tid & 31;
    int w    = tid >> 5;               // warp 0..7

    __shared__ alignas(16) char sA[TILE_ROWS * SROW_BYTES];   // 18 KB
    __shared__ alignas(16) char sB[TILE_COLS * SROW_BYTES];   // 18 KB
    __shared__ float partial[8][TILE_COLS];                   // 4 KB

    // stage B (Y rows colbase..colbase+127) once
    stage_tile(sB, &g_Yb[b][colbase][0], tid);

    // ldmatrix lane-address components
    uint32_t sA_base = smem_u32(sA);
    uint32_t sB_base = smem_u32(sB);
    // A x4: lanes 0-7 m0-7@k0 | 8-15 m8-15@k0 | 16-23 m0-7@k8 | 24-31 m8-15@k8
    uint32_t aAddr = sA_base + (uint32_t)((w * 16 + (lane & 15)) * SROW_BYTES
                                          + ((lane >> 4) & 1) * 16);
    // B x4 trans: lanes 0-7 n0-7@k0 | 8-15 n0-7@k8 | 16-23 n8-15@k0 | 24-31 n8-15@k8
    uint32_t bAddr = sB_base + (uint32_t)((((lane & 7) + ((lane >> 4) & 1) * 8) * SROW_BYTES)
                                          + ((lane >> 3) & 1) * 16);

    float colacc[32];                  // 2 cols per n8 tile x 16 tiles
    #pragma unroll
    for (int i = 0; i < 32; ++i) colacc[i] = 0.0f;

    int ntiles = (nx + TILE_ROWS - 1) / TILE_ROWS;
    for (int t = 0; t < ntiles; ++t) {
        __syncthreads();
        stage_tile(sA, &g_Xb[b][t * TILE_ROWS][0], tid);
        __syncthreads();

        // hoist A fragments for all 4 k-steps (warp's 16-row slab)
        uint32_t afr[4][4];
        #pragma unroll
        for (int ks = 0; ks < 4; ++ks)
            ldsm_x4(aAddr + ks * 32, afr[ks]);

        #pragma unroll
        for (int nt = 0; nt < 8; ++nt) {           // n16 tiles
            float c0[4] = {0.f, 0.f, 0.f, 0.f};
            float c1[4] = {0.f, 0.f, 0.f, 0.f};
            #pragma unroll
            for (int ks = 0; ks < 4; ++ks) {
                uint32_t bfr[4];
                ldsm_x4_trans(bAddr + nt * 16 * SROW_BYTES + ks * 32, bfr);
                mma_bf16(c0, afr[ks], bfr[0], bfr[1]);   // n8 sub-tile 0
                mma_bf16(c1, afr[ks], bfr[2], bfr[3]);   // n8 sub-tile 1
            }
            // exp(10*d - 10), summed over this thread's two rows
            colacc[nt*4 + 0] += __expf(fmaf(c0[0], 10.f, -10.f))
                              + __expf(fmaf(c0[2], 10.f, -10.f));
            colacc[nt*4 + 1] += __expf(fmaf(c0[1], 10.f, -10.f))
                              + __expf(fmaf(c0[3], 10.f, -10.f));
            colacc[nt*4 + 2] += __expf(fmaf(c1[0], 10.f, -10.f))
                              + __expf(fmaf(c1[2], 10.f, -10.f));
            colacc[nt*4 + 3] += __expf(fmaf(c1[1], 10.f, -10.f))
                              + __expf(fmaf(c1[3], 10.f, -10.f));
        }
    }

    // reduce over groupID (8 row-owners per column): lanes g*4+tig, tig = lane&3
    #pragma unroll
    for (int e = 0; e < 32; ++e) {
        float v = colacc[e];
        v += __shfl_xor_sync(0xffffffffu, v, 4);
        v += __shfl_xor_sync(0xffffffffu, v, 8);
        v += __shfl_xor_sync(0xffffffffu, v, 16);
        if (lane < 4) {
            int nt = e >> 2, sub = (e >> 1) & 1, q = e & 1;
            partial[w][nt * 16 + sub * 8 + lane * 2 + q] = v;
        }
    }
    __syncthreads();

    if (tid < TILE_COLS) {
        float S = 0.0f;
        #pragma unroll
        for (int i = 0; i < 8; ++i) S += partial[i][tid];
        S -= (float)(ntiles * TILE_ROWS - nx) * __expf(-10.0f);  // exact pad removal
        int c = colbase + tid;
        if (c < m) g_percol[b][c] = 10.0f + logf(S);
    }
}

// ============================================================
// Kernel 4a: per-batch reduction, coalesced bf16 diag recompute
// grid: B blocks x 1024 threads (32 warps, warp = one row at a time)
// ============================================================
__global__ void reduce_batch_kernel() {
    int b    = blockIdx.x;
    int tid  = threadIdx.x;
    int lane = tid & 31;
    int w    = tid >> 5;
    int m    = min(g_nx[b], g_ny[b]);
    __shared__ float wsum[32];

    float s = 0.0f;
    for (int j = w; j < m; j += 32) {
        __nv_bfloat162 xv = *reinterpret_cast<const __nv_bfloat162*>(&g_Xb[b][j][lane * 2]);
        __nv_bfloat162 yv = *reinterpret_cast<const __nv_bfloat162*>(&g_Yb[b][j][lane * 2]);
        float2 xf = __bfloat1622float2(xv);
        float2 yf = __bfloat1622float2(yv);
        float d = xf.x * yf.x + xf.y * yf.y;
        #pragma unroll
        for (int o = 16; o > 0; o >>= 1) d += __shfl_xor_sync(0xffffffffu, d, o);
        if (lane == 0) s += g_percol[b][j] - 10.0f * d;   // lse - diag
    }
    if (lane == 0) wsum[w] = s;
    __syncthreads();
    if (tid < 32) {
        float v = wsum[tid];
        #pragma unroll
        for (int o = 16; o > 0; o >>= 1) v += __shfl_xor_sync(0xffffffffu, v, o);
        if (tid == 0) g_batchloss[b] = (m > 0) ? v / (float)m : 0.0f;
    }
}

// ============================================================
// Kernel 4b: combine 8 batch losses -> scalar mean
// ============================================================
__global__ void combine_kernel(float* __restrict__ out) {
    if (threadIdx.x == 0) {
        float t = 0.0f;
        #pragma unroll
        for (int b = 0; b < B; ++b) t += g_batchloss[b];
        out[0] = t / (float)B;
    }
}

// ============================================================
extern "C" void kernel_launch(void* const* d_in, const int* in_sizes, int n_in,
                              void* d_out, int out_size) {
    const float* x   = (const float*)d_in[0];
    const float* y   = (const float*)d_in[1];
    const int*   im1 = (const int*)d_in[2];
    const int*   im2 = (const int*)d_in[3];
    const int*   sh1 = (const int*)d_in[4];
    const int*   sh2 = (const int*)d_in[5];

    compact_kernel<<<B, 1024>>>(im1, im2, sh1, sh2);
    gather_norm_kernel<<<dim3(T / 8, B, 2), 256>>>(x, y);
    simloss_mma_kernel<<<dim3(T / TILE_COLS, B), 256>>>();
    reduce_batch_kernel<<<B, 1024>>>();
    combine_kernel<<<1, 32>>>((float*)d_out);
}

// round 14
// speedup vs baseline: 4.4196x; 1.2523x over previous
#include <cuda_runtime.h>
#include <cuda_bf16.h>
#include <math.h>
#include <cstdint>

// Problem shape (fixed by the dataset): B=8, T=4096, D=64
constexpr int B = 8;
constexpr int T = 4096;
constexpr int D = 64;

// ---------------- device scratch (no allocations allowed) ----------------
__device__ __nv_bfloat16 g_Xb[B][T][D];   // normalized selected rows of x (bf16), zero-padded
__device__ __nv_bfloat16 g_Yb[B][T][D];   // normalized selected rows of y (bf16), zero-padded
__device__ int   g_rsel[B][T];
__device__ int   g_csel[B][T];
__device__ int   g_nx[B];
__device__ int   g_ny[B];
__device__ float g_tilesum[B][T / 128];   // per-CTA sum of (lse - diag) over its columns

// ---------------- mma.sync / ldmatrix wrappers (plain sm_103 legal) -------
__device__ __forceinline__ uint32_t smem_u32(const void* p) {
    return (uint32_t)__cvta_generic_to_shared(p);
}
__device__ __forceinline__ void ldsm_x4(uint32_t addr, uint32_t r[4]) {
    asm volatile("ldmatrix.sync.aligned.m8n8.x4.shared.b16 {%0,%1,%2,%3}, [%4];"
                 : "=r"(r[0]), "=r"(r[1]), "=r"(r[2]), "=r"(r[3]) : "r"(addr));
}
__device__ __forceinline__ void ldsm_x4_trans(uint32_t addr, uint32_t r[4]) {
    asm volatile("ldmatrix.sync.aligned.m8n8.x4.trans.shared.b16 {%0,%1,%2,%3}, [%4];"
                 : "=r"(r[0]), "=r"(r[1]), "=r"(r[2]), "=r"(r[3]) : "r"(addr));
}
__device__ __forceinline__ void mma_bf16(float c[4], const uint32_t a[4],
                                         uint32_t b0, uint32_t b1) {
    asm volatile(
        "mma.sync.aligned.m16n8k16.row.col.f32.bf16.bf16.f32 "
        "{%0,%1,%2,%3}, {%4,%5,%6,%7}, {%8,%9}, {%0,%1,%2,%3};"
        : "+f"(c[0]), "+f"(c[1]), "+f"(c[2]), "+f"(c[3])
        : "r"(a[0]), "r"(a[1]), "r"(a[2]), "r"(a[3]), "r"(b0), "r"(b1));
}

// ============================================================
// Kernel 1: stable compaction of selected indices (per batch)
// ============================================================
__global__ void compact_kernel(const int* __restrict__ im1, const int* __restrict__ im2,
                               const int* __restrict__ sh1, const int* __restrict__ sh2) {
    int b   = blockIdx.x;
    int tid = threadIdx.x;
    int lane = tid & 31, wid = tid >> 5;
    __shared__ int wtot[32];

    for (int sel = 0; sel < 2; ++sel) {
        const int* im = sel ? im2 : im1;
        const int* sh = sel ? sh2 : sh1;
        int* outp = sel ? &g_csel[b][0] : &g_rsel[b][0];

        int t0 = tid * 4;
        int v[4];
        int cnt = 0;
        #pragma unroll
        for (int i = 0; i < 4; ++i) {
            int t = t0 + i;
            v[i] = (im[b * T + t] != 0 && sh[b * T + t] != 0) ? 1 : 0;
            cnt += v[i];
        }
        int incl = cnt;
        #pragma unroll
        for (int o = 1; o < 32; o <<= 1) {
            int tt = __shfl_up_sync(0xffffffffu, incl, o);
            if (lane >= o) incl += tt;
        }
        if (lane == 31) wtot[wid] = incl;
        __syncthreads();
        if (wid == 0) {
            int val  = wtot[lane];
            int winc = val;
            #pragma unroll
            for (int o = 1; o < 32; o <<= 1) {
                int tt = __shfl_up_sync(0xffffffffu, winc, o);
                if (lane >= o) winc += tt;
            }
            wtot[lane] = winc - val;
            if (lane == 31) {
                if (sel) g_ny[b] = winc; else g_nx[b] = winc;
            }
        }
        __syncthreads();
        int off = wtot[wid] + (incl - cnt);
        #pragma unroll
        for (int i = 0; i < 4; ++i)
            if (v[i]) outp[off++] = t0 + i;
        __syncthreads();
    }
}

// ============================================================
// Kernel 2: gather selected rows + L2-normalize -> bf16 tiles
// ============================================================
__global__ void gather_norm_kernel(const float* __restrict__ x, const float* __restrict__ y) {
    int b     = blockIdx.y;
    int which = blockIdx.z;
    int wid  = threadIdx.x >> 5;
    int lane = threadIdx.x & 31;
    int p = blockIdx.x * 8 + wid;

    int count = which ? g_ny[b] : g_nx[b];
    if (p >= count) return;
    int r = which ? g_csel[b][p] : g_rsel[b][p];

    const float* src = (which ? y : x) + ((size_t)b * T + r) * D;
    float2 v = reinterpret_cast<const float2*>(src)[lane];
    float ss = v.x * v.x + v.y * v.y;
    #pragma unroll
    for (int o = 16; o > 0; o >>= 1) ss += __shfl_xor_sync(0xffffffffu, ss, o);
    float sc = 1.0f / fmaxf(sqrtf(ss), 1e-12f);

    __nv_bfloat16* dst = which ? &g_Yb[b][p][0] : &g_Xb[b][p][0];
    reinterpret_cast<__nv_bfloat162*>(dst)[lane] =
        __floats2bfloat162_rn(v.x * sc, v.y * sc);
}

// ============================================================
// Kernel 3: HMMA GEMM + fixed-shift column exp-sums + fused
// per-column diag recompute (proven fp32-dot path) + per-CTA sum.
// grid: (T/128, B), block 256 (8 warps). CTA owns 128 sim columns.
// ============================================================
constexpr int TILE_ROWS  = 128;
constexpr int TILE_COLS  = 128;
constexpr int SROW_BYTES = 144;          // 64 bf16 = 128B data + 16B pad

__device__ __forceinline__ void stage_tile(char* dst, const __nv_bfloat16* src, int tid) {
    #pragma unroll
    for (int i = 0; i < 4; ++i) {
        int g = i * 256 + tid;
        int row = g >> 3, chunk = g & 7;
        uint4 v = *reinterpret_cast<const uint4*>(src + row * D + chunk * 8);
        *reinterpret_cast<uint4*>(dst + row * SROW_BYTES + chunk * 16) = v;
    }
}

__global__ void __launch_bounds__(256)
simloss_mma_kernel() {
    int b  = blockIdx.y;
    int nx = g_nx[b];
    int ny = g_ny[b];
    int m  = min(nx, ny);
    int colbase = blockIdx.x * TILE_COLS;
    if (colbase >= m) return;
    (void)ny;

    int tid  = threadIdx.x;
    int lane = tid & 31;
    int w    = tid >> 5;               // warp 0..7

    __shared__ alignas(16) char sA[TILE_ROWS * SROW_BYTES];   // 18 KB
    __shared__ alignas(16) char sB[TILE_COLS * SROW_BYTES];   // 18 KB
    __shared__ float partial[8][TILE_COLS];                   // 4 KB
    __shared__ float redsum[8];

    // stage B (Y rows colbase..colbase+127) once
    stage_tile(sB, &g_Yb[b][colbase][0], tid);

    uint32_t sA_base = smem_u32(sA);
    uint32_t sB_base = smem_u32(sB);
    uint32_t aAddr = sA_base + (uint32_t)((w * 16 + (lane & 15)) * SROW_BYTES
                                          + ((lane >> 4) & 1) * 16);
    uint32_t bAddr = sB_base + (uint32_t)((((lane & 7) + ((lane >> 4) & 1) * 8) * SROW_BYTES)
                                          + ((lane >> 3) & 1) * 16);

    float colacc[32];
    #pragma unroll
    for (int i = 0; i < 32; ++i) colacc[i] = 0.0f;

    int ntiles = (nx + TILE_ROWS - 1) / TILE_ROWS;
    for (int t = 0; t < ntiles; ++t) {
        __syncthreads();
        stage_tile(sA, &g_Xb[b][t * TILE_ROWS][0], tid);
        __syncthreads();

        uint32_t afr[4][4];
        #pragma unroll
        for (int ks = 0; ks < 4; ++ks)
            ldsm_x4(aAddr + ks * 32, afr[ks]);

        #pragma unroll
        for (int nt = 0; nt < 8; ++nt) {           // n16 tiles
            float c0[4] = {0.f, 0.f, 0.f, 0.f};
            float c1[4] = {0.f, 0.f, 0.f, 0.f};
            #pragma unroll
            for (int ks = 0; ks < 4; ++ks) {
                uint32_t bfr[4];
                ldsm_x4_trans(bAddr + nt * 16 * SROW_BYTES + ks * 32, bfr);
                mma_bf16(c0, afr[ks], bfr[0], bfr[1]);   // n8 sub-tile 0
                mma_bf16(c1, afr[ks], bfr[2], bfr[3]);   // n8 sub-tile 1
            }
            colacc[nt*4 + 0] += __expf(fmaf(c0[0], 10.f, -10.f))
                              + __expf(fmaf(c0[2], 10.f, -10.f));
            colacc[nt*4 + 1] += __expf(fmaf(c0[1], 10.f, -10.f))
                              + __expf(fmaf(c0[3], 10.f, -10.f));
            colacc[nt*4 + 2] += __expf(fmaf(c1[0], 10.f, -10.f))
                              + __expf(fmaf(c1[2], 10.f, -10.f));
            colacc[nt*4 + 3] += __expf(fmaf(c1[1], 10.f, -10.f))
                              + __expf(fmaf(c1[3], 10.f, -10.f));
        }
    }

    // reduce over the 8 row-owner lanes per column (column mapping validated R10)
    #pragma unroll
    for (int e = 0; e < 32; ++e) {
        float v = colacc[e];
        v += __shfl_xor_sync(0xffffffffu, v, 4);
        v += __shfl_xor_sync(0xffffffffu, v, 8);
        v += __shfl_xor_sync(0xffffffffu, v, 16);
        if (lane < 4) {
            int nt = e >> 2, sub = (e >> 1) & 1, q = e & 1;
            partial[w][nt * 16 + sub * 8 + lane * 2 + q] = v;
        }
    }
    __syncthreads();

    // per-column term = lse - diag (diag recomputed fp32 from the same bf16
    // values -- identical math to the R10-validated path), then block-sum.
    float term = 0.0f;
    if (tid < TILE_COLS) {
        int c = colbase + tid;
        if (c < m) {
            float S = 0.0f;
            #pragma unroll
            for (int i = 0; i < 8; ++i) S += partial[i][tid];
            S -= (float)(ntiles * TILE_ROWS - nx) * __expf(-10.0f);  // exact pad removal

            // coalesced: consecutive threads read consecutive 128B rows (L2-hot)
            float dsum = 0.0f;
            const uint4* xp = reinterpret_cast<const uint4*>(&g_Xb[b][c][0]);
            const uint4* yp = reinterpret_cast<const uint4*>(&g_Yb[b][c][0]);
            #pragma unroll
            for (int k = 0; k < 8; ++k) {
                uint4 xv = xp[k], yv = yp[k];
                const __nv_bfloat162* xh = reinterpret_cast<const __nv_bfloat162*>(&xv);
                const __nv_bfloat162* yh = reinterpret_cast<const __nv_bfloat162*>(&yv);
                #pragma unroll
                for (int j = 0; j < 4; ++j) {
                    float2 xf = __bfloat1622float2(xh[j]);
                    float2 yf = __bfloat1622float2(yh[j]);
                    dsum += xf.x * yf.x + xf.y * yf.y;
                }
            }
            term = 10.0f + logf(S) - 10.0f * dsum;
        }
    }
    #pragma unroll
    for (int o = 16; o > 0; o >>= 1) term += __shfl_xor_sync(0xffffffffu, term, o);
    if (lane == 0) redsum[w] = term;
    __syncthreads();
    if (tid == 0) {
        float s = 0.0f;
        #pragma unroll
        for (int i = 0; i < 8; ++i) s += redsum[i];
        g_tilesum[b][blockIdx.x] = s;
    }
}

// ============================================================
// Kernel 4: combine tile partials -> scalar mean loss
// ============================================================
__global__ void combine_kernel(float* __restrict__ out) {
    int lane = threadIdx.x & 31;
    if (threadIdx.x < 32) {
        float lb = 0.0f;
        if (lane < B) {
            int m = min(g_nx[lane], g_ny[lane]);
            int ntc = (m + 127) / 128;          // active column tiles
            float s = 0.0f;
            for (int i = 0; i < ntc; ++i) s += g_tilesum[lane][i];
            lb = (m > 0) ? s / (float)m : 0.0f;
        }
        #pragma unroll
        for (int o = 4; o > 0; o >>= 1) lb += __shfl_xor_sync(0xffffffffu, lb, o);
        if (lane == 0) out[0] = lb / (float)B;
    }
}

// ============================================================
extern "C" void kernel_launch(void* const* d_in, const int* in_sizes, int n_in,
                              void* d_out, int out_size) {
    const float* x   = (const float*)d_in[0];
    const float* y   = (const float*)d_in[1];
    const int*   im1 = (const int*)d_in[2];
    const int*   im2 = (const int*)d_in[3];
    const int*   sh1 = (const int*)d_in[4];
    const int*   sh2 = (const int*)d_in[5];

    compact_kernel<<<B, 1024>>>(im1, im2, sh1, sh2);
    gather_norm_kernel<<<dim3(T / 8, B, 2), 256>>>(x, y);
    simloss_mma_kernel<<<dim3(T / TILE_COLS, B), 256>>>();
    combine_kernel<<<1, 32>>>((float*)d_out);
}

// round 15
// speedup vs baseline: 5.0842x; 1.1504x over previous
#include <cuda_runtime.h>
#include <cuda_bf16.h>
#include <math.h>
#include <cstdint>

// Problem shape (fixed by the dataset): B=8, T=4096, D=64
constexpr int B = 8;
constexpr int T = 4096;
constexpr int D = 64;

// ---------------- device scratch (no allocations allowed) ----------------
__device__ __nv_bfloat16 g_Xb[B][T][D];   // normalized selected rows of x (bf16), zero-padded
__device__ __nv_bfloat16 g_Yb[B][T][D];   // normalized selected rows of y (bf16), zero-padded
__device__ int   g_rsel[B][T];
__device__ int   g_csel[B][T];
__device__ int   g_nx[B];
__device__ int   g_ny[B];
__device__ float g_tilesum[B][T / 128];   // per-CTA sum of (lse - diag) over its columns

// ---------------- mma.sync / ldmatrix wrappers (plain sm_103 legal) -------
__device__ __forceinline__ uint32_t smem_u32(const void* p) {
    return (uint32_t)__cvta_generic_to_shared(p);
}
__device__ __forceinline__ void ldsm_x4(uint32_t addr, uint32_t r[4]) {
    asm volatile("ldmatrix.sync.aligned.m8n8.x4.shared.b16 {%0,%1,%2,%3}, [%4];"
                 : "=r"(r[0]), "=r"(r[1]), "=r"(r[2]), "=r"(r[3]) : "r"(addr));
}
__device__ __forceinline__ void ldsm_x4_trans(uint32_t addr, uint32_t r[4]) {
    asm volatile("ldmatrix.sync.aligned.m8n8.x4.trans.shared.b16 {%0,%1,%2,%3}, [%4];"
                 : "=r"(r[0]), "=r"(r[1]), "=r"(r[2]), "=r"(r[3]) : "r"(addr));
}
__device__ __forceinline__ void mma_bf16(float c[4], const uint32_t a[4],
                                         uint32_t b0, uint32_t b1) {
    asm volatile(
        "mma.sync.aligned.m16n8k16.row.col.f32.bf16.bf16.f32 "
        "{%0,%1,%2,%3}, {%4,%5,%6,%7}, {%8,%9}, {%0,%1,%2,%3};"
        : "+f"(c[0]), "+f"(c[1]), "+f"(c[2]), "+f"(c[3])
        : "r"(a[0]), "r"(a[1]), "r"(a[2]), "r"(a[3]), "r"(b0), "r"(b1));
}
// exp(10*d - 10) = 2^(d*10*log2e - 10*log2e), single FFMA + MUFU.EX2
constexpr float L2E10 = 14.4269504088896341f;   // 10 * log2(e)
__device__ __forceinline__ float exp10s(float d) {
    float e;
    asm("ex2.approx.ftz.f32 %0, %1;" : "=f"(e) : "f"(fmaf(d, L2E10, -L2E10)));
    return e;
}

// ============================================================
// Kernel 1: stable compaction of selected indices (per batch)
// ============================================================
__global__ void compact_kernel(const int* __restrict__ im1, const int* __restrict__ im2,
                               const int* __restrict__ sh1, const int* __restrict__ sh2) {
    int b   = blockIdx.x;
    int tid = threadIdx.x;
    int lane = tid & 31, wid = tid >> 5;
    __shared__ int wtot[32];

    for (int sel = 0; sel < 2; ++sel) {
        const int* im = sel ? im2 : im1;
        const int* sh = sel ? sh2 : sh1;
        int* outp = sel ? &g_csel[b][0] : &g_rsel[b][0];

        int t0 = tid * 4;
        int v[4];
        int cnt = 0;
        #pragma unroll
        for (int i = 0; i < 4; ++i) {
            int t = t0 + i;
            v[i] = (im[b * T + t] != 0 && sh[b * T + t] != 0) ? 1 : 0;
            cnt += v[i];
        }
        int incl = cnt;
        #pragma unroll
        for (int o = 1; o < 32; o <<= 1) {
            int tt = __shfl_up_sync(0xffffffffu, incl, o);
            if (lane >= o) incl += tt;
        }
        if (lane == 31) wtot[wid] = incl;
        __syncthreads();
        if (wid == 0) {
            int val  = wtot[lane];
            int winc = val;
            #pragma unroll
            for (int o = 1; o < 32; o <<= 1) {
                int tt = __shfl_up_sync(0xffffffffu, winc, o);
                if (lane >= o) winc += tt;
            }
            wtot[lane] = winc - val;
            if (lane == 31) {
                if (sel) g_ny[b] = winc; else g_nx[b] = winc;
            }
        }
        __syncthreads();
        int off = wtot[wid] + (incl - cnt);
        #pragma unroll
        for (int i = 0; i < 4; ++i)
            if (v[i]) outp[off++] = t0 + i;
        __syncthreads();
    }
}

// ============================================================
// Kernel 2: gather selected rows + L2-normalize -> bf16 tiles
// ============================================================
__global__ void gather_norm_kernel(const float* __restrict__ x, const float* __restrict__ y) {
    int b     = blockIdx.y;
    int which = blockIdx.z;
    int wid  = threadIdx.x >> 5;
    int lane = threadIdx.x & 31;
    int p = blockIdx.x * 8 + wid;

    int count = which ? g_ny[b] : g_nx[b];
    if (p >= count) return;
    int r = which ? g_csel[b][p] : g_rsel[b][p];

    const float* src = (which ? y : x) + ((size_t)b * T + r) * D;
    float2 v = reinterpret_cast<const float2*>(src)[lane];
    float ss = v.x * v.x + v.y * v.y;
    #pragma unroll
    for (int o = 16; o > 0; o >>= 1) ss += __shfl_xor_sync(0xffffffffu, ss, o);
    float sc = 1.0f / fmaxf(sqrtf(ss), 1e-12f);

    __nv_bfloat16* dst = which ? &g_Yb[b][p][0] : &g_Xb[b][p][0];
    reinterpret_cast<__nv_bfloat162*>(dst)[lane] =
        __floats2bfloat162_rn(v.x * sc, v.y * sc);
}

// ============================================================
// Kernel 3: HMMA GEMM + fixed-shift column exp-sums + fused diag
// + per-CTA sum. Double-buffered sA with register prefetch:
// LDG for tile t+1 overlaps MMA/exp of tile t; ONE sync per tile.
// grid: (T/128, B), block 256 (8 warps). CTA owns 128 sim columns.
// ============================================================
constexpr int TILE_ROWS  = 128;
constexpr int TILE_COLS  = 128;
constexpr int SROW_BYTES = 144;          // 64 bf16 = 128B data + 16B pad

__global__ void __launch_bounds__(256)
simloss_mma_kernel() {
    int b  = blockIdx.y;
    int nx = g_nx[b];
    int ny = g_ny[b];
    int m  = min(nx, ny);
    int colbase = blockIdx.x * TILE_COLS;
    if (colbase >= m) return;
    (void)ny;

    int tid  = threadIdx.x;
    int lane = tid & 31;
    int w    = tid >> 5;               // warp 0..7

    __shared__ alignas(16) char sA[2][TILE_ROWS * SROW_BYTES];  // 2 x 18 KB
    __shared__ alignas(16) char sB[TILE_COLS * SROW_BYTES];     // 18 KB
    __shared__ float partial[8][TILE_COLS];                     // 4 KB
    __shared__ float redsum[8];

    // this thread's 4 staging slots (row, chunk) and their smem offsets
    int srow[4], soff[4];
    const __nv_bfloat16* gsrc[4];
    #pragma unroll
    for (int i = 0; i < 4; ++i) {
        int g = i * 256 + tid;
        srow[i] = g >> 3;
        int chunk = g & 7;
        soff[i] = srow[i] * SROW_BYTES + chunk * 16;
        gsrc[i] = nullptr;
    }

    // stage B (Y rows colbase..colbase+127) once
    {
        const __nv_bfloat16* srcb = &g_Yb[b][colbase][0];
        #pragma unroll
        for (int i = 0; i < 4; ++i) {
            int g = i * 256 + tid;
            uint4 v = *reinterpret_cast<const uint4*>(srcb + srow[i] * D + (g & 7) * 8);
            *reinterpret_cast<uint4*>(sB + soff[i]) = v;
        }
    }

    uint32_t sB_base = smem_u32(sB);
    uint32_t aOff = (uint32_t)((w * 16 + (lane & 15)) * SROW_BYTES
                               + ((lane >> 4) & 1) * 16);
    uint32_t bAddr = sB_base + (uint32_t)((((lane & 7) + ((lane >> 4) & 1) * 8) * SROW_BYTES)
                                          + ((lane >> 3) & 1) * 16);

    float colacc[32];
    #pragma unroll
    for (int i = 0; i < 32; ++i) colacc[i] = 0.0f;

    int ntiles = (nx + TILE_ROWS - 1) / TILE_ROWS;

    // prologue: stage tile 0 into sA[0]
    {
        const __nv_bfloat16* src0 = &g_Xb[b][0][0];
        #pragma unroll
        for (int i = 0; i < 4; ++i) {
            int g = i * 256 + tid;
            uint4 v = *reinterpret_cast<const uint4*>(src0 + srow[i] * D + (g & 7) * 8);
            *reinterpret_cast<uint4*>(sA[0] + soff[i]) = v;
        }
    }
    __syncthreads();

    int cur = 0;
    for (int t = 0; t < ntiles; ++t) {
        // prefetch tile t+1 into registers (overlaps compute below)
        uint4 pf[4];
        bool havenext = (t + 1 < ntiles);
        if (havenext) {
            const __nv_bfloat16* srcn = &g_Xb[b][(t + 1) * TILE_ROWS][0];
            #pragma unroll
            for (int i = 0; i < 4; ++i) {
                int g = i * 256 + tid;
                pf[i] = *reinterpret_cast<const uint4*>(srcn + srow[i] * D + (g & 7) * 8);
            }
        }

        uint32_t aAddr = smem_u32(sA[cur]) + aOff;
        uint32_t afr[4][4];
        #pragma unroll
        for (int ks = 0; ks < 4; ++ks)
            ldsm_x4(aAddr + ks * 32, afr[ks]);

        #pragma unroll
        for (int nt = 0; nt < 8; ++nt) {           // n16 tiles
            float c0[4] = {0.f, 0.f, 0.f, 0.f};
            float c1[4] = {0.f, 0.f, 0.f, 0.f};
            #pragma unroll
            for (int ks = 0; ks < 4; ++ks) {
                uint32_t bfr[4];
                ldsm_x4_trans(bAddr + nt * 16 * SROW_BYTES + ks * 32, bfr);
                mma_bf16(c0, afr[ks], bfr[0], bfr[1]);   // n8 sub-tile 0
                mma_bf16(c1, afr[ks], bfr[2], bfr[3]);   // n8 sub-tile 1
            }
            colacc[nt*4 + 0] += exp10s(c0[0]) + exp10s(c0[2]);
            colacc[nt*4 + 1] += exp10s(c0[1]) + exp10s(c0[3]);
            colacc[nt*4 + 2] += exp10s(c1[0]) + exp10s(c1[2]);
            colacc[nt*4 + 3] += exp10s(c1[1]) + exp10s(c1[3]);
        }

        if (havenext) {
            #pragma unroll
            for (int i = 0; i < 4; ++i)
                *reinterpret_cast<uint4*>(sA[cur ^ 1] + soff[i]) = pf[i];
        }
        __syncthreads();
        cur ^= 1;
    }

    // reduce over the 8 row-owner lanes per column (column mapping validated R10)
    #pragma unroll
    for (int e = 0; e < 32; ++e) {
        float v = colacc[e];
        v += __shfl_xor_sync(0xffffffffu, v, 4);
        v += __shfl_xor_sync(0xffffffffu, v, 8);
        v += __shfl_xor_sync(0xffffffffu, v, 16);
        if (lane < 4) {
            int nt = e >> 2, sub = (e >> 1) & 1, q = e & 1;
            partial[w][nt * 16 + sub * 8 + lane * 2 + q] = v;
        }
    }
    __syncthreads();

    // per-column term = lse - diag (diag recomputed fp32 from the same bf16
    // values -- validated path), then block-sum -> one float per CTA
    float term = 0.0f;
    if (tid < TILE_COLS) {
        int c = colbase + tid;
        if (c < m) {
            float S = 0.0f;
            #pragma unroll
            for (int i = 0; i < 8; ++i) S += partial[i][tid];
            S -= (float)(ntiles * TILE_ROWS - nx) * __expf(-10.0f);  // exact pad removal

            float dsum = 0.0f;
            const uint4* xp = reinterpret_cast<const uint4*>(&g_Xb[b][c][0]);
            const uint4* yp = reinterpret_cast<const uint4*>(&g_Yb[b][c][0]);
            #pragma unroll
            for (int k = 0; k < 8; ++k) {
                uint4 xv = xp[k], yv = yp[k];
                const __nv_bfloat162* xh = reinterpret_cast<const __nv_bfloat162*>(&xv);
                const __nv_bfloat162* yh = reinterpret_cast<const __nv_bfloat162*>(&yv);
                #pragma unroll
                for (int j = 0; j < 4; ++j) {
                    float2 xf = __bfloat1622float2(xh[j]);
                    float2 yf = __bfloat1622float2(yh[j]);
                    dsum += xf.x * yf.x + xf.y * yf.y;
                }
            }
            term = 10.0f + logf(S) - 10.0f * dsum;
        }
    }
    #pragma unroll
    for (int o = 16; o > 0; o >>= 1) term += __shfl_xor_sync(0xffffffffu, term, o);
    if (lane == 0) redsum[w] = term;
    __syncthreads();
    if (tid == 0) {
        float s = 0.0f;
        #pragma unroll
        for (int i = 0; i < 8; ++i) s += redsum[i];
        g_tilesum[b][blockIdx.x] = s;
    }
}

// ============================================================
// Kernel 4: combine tile partials -> scalar mean loss
// 256 threads: warp w owns batch w (lane = tile idx), parallel loads.
// ============================================================
__global__ void combine_kernel(float* __restrict__ out) {
    int w    = threadIdx.x >> 5;
    int lane = threadIdx.x & 31;
    __shared__ float sb[8];

    int m   = min(g_nx[w], g_ny[w]);
    int ntc = (m + 127) / 128;              // <= 32 tiles
    float s = (lane < ntc) ? g_tilesum[w][lane] : 0.0f;
    #pragma unroll
    for (int o = 16; o > 0; o >>= 1) s += __shfl_xor_sync(0xffffffffu, s, o);
    if (lane == 0) sb[w] = (m > 0) ? s / (float)m : 0.0f;
    __syncthreads();
    if (threadIdx.x == 0) {
        float t = 0.0f;
        #pragma unroll
        for (int i = 0; i < 8; ++i) t += sb[i];
        out[0] = t / (float)B;
    }
}

// ============================================================
extern "C" void kernel_launch(void* const* d_in, const int* in_sizes, int n_in,
                              void* d_out, int out_size) {
    const float* x   = (const float*)d_in[0];
    const float* y   = (const float*)d_in[1];
    const int*   im1 = (const int*)d_in[2];
    const int*   im2 = (const int*)d_in[3];
    const int*   sh1 = (const int*)d_in[4];
    const int*   sh2 = (const int*)d_in[5];

    compact_kernel<<<B, 1024>>>(im1, im2, sh1, sh2);
    gather_norm_kernel<<<dim3(T / 8, B, 2), 256>>>(x, y);
    simloss_mma_kernel<<<dim3(T / TILE_COLS, B), 256>>>();
    combine_kernel<<<1, 256>>>((float*)d_out);
}

// round 17
// speedup vs baseline: 6.6688x; 1.3117x over previous
#include <cuda_runtime.h>
#include <cuda_bf16.h>
#include <math.h>
#include <cstdint>

// Problem shape (fixed by the dataset): B=8, T=4096, D=64
constexpr int B = 8;
constexpr int T = 4096;
constexpr int D = 64;

// ---------------- device scratch (no allocations allowed) ----------------
__device__ __nv_bfloat16 g_Xb[B][T][D];   // normalized selected rows of x (bf16), zero-padded
__device__ __nv_bfloat16 g_Yb[B][T][D];   // normalized selected rows of y (bf16), zero-padded
__device__ int      g_rsel[B][T];
__device__ int      g_csel[B][T];
__device__ int      g_nx[B];
__device__ int      g_ny[B];
__device__ float    g_tilesum[B][T / 64]; // per-CTA sum of (lse - diag) over its columns
__device__ unsigned g_count;              // last-CTA arrival counter (self-resetting)

// ---------------- mma.sync / ldmatrix wrappers (plain sm_103 legal) -------
__device__ __forceinline__ uint32_t smem_u32(const void* p) {
    return (uint32_t)__cvta_generic_to_shared(p);
}
__device__ __forceinline__ void ldsm_x4(uint32_t addr, uint32_t r[4]) {
    asm volatile("ldmatrix.sync.aligned.m8n8.x4.shared.b16 {%0,%1,%2,%3}, [%4];"
                 : "=r"(r[0]), "=r"(r[1]), "=r"(r[2]), "=r"(r[3]) : "r"(addr));
}
__device__ __forceinline__ void ldsm_x4_trans(uint32_t addr, uint32_t r[4]) {
    asm volatile("ldmatrix.sync.aligned.m8n8.x4.trans.shared.b16 {%0,%1,%2,%3}, [%4];"
                 : "=r"(r[0]), "=r"(r[1]), "=r"(r[2]), "=r"(r[3]) : "r"(addr));
}
__device__ __forceinline__ void mma_bf16(float c[4], const uint32_t a[4],
                                         uint32_t b0, uint32_t b1) {
    asm volatile(
        "mma.sync.aligned.m16n8k16.row.col.f32.bf16.bf16.f32 "
        "{%0,%1,%2,%3}, {%4,%5,%6,%7}, {%8,%9}, {%0,%1,%2,%3};"
        : "+f"(c[0]), "+f"(c[1]), "+f"(c[2]), "+f"(c[3])
        : "r"(a[0]), "r"(a[1]), "r"(a[2]), "r"(a[3]), "r"(b0), "r"(b1));
}
// exp(10*d - 10) = 2^(d*10*log2e - 10*log2e), single FFMA + MUFU.EX2
constexpr float L2E10 = 14.4269504088896341f;   // 10 * log2(e)
__device__ __forceinline__ float exp10s(float d) {
    float e;
    asm("ex2.approx.ftz.f32 %0, %1;" : "=f"(e) : "f"(fmaf(d, L2E10, -L2E10)));
    return e;
}

// ============================================================
// Kernel 1: stable compaction of selected indices (per batch)
// ============================================================
__global__ void compact_kernel(const int* __restrict__ im1, const int* __restrict__ im2,
                               const int* __restrict__ sh1, const int* __restrict__ sh2) {
    int b   = blockIdx.x;
    int tid = threadIdx.x;
    int lane = tid & 31, wid = tid >> 5;
    __shared__ int wtot[32];

    for (int sel = 0; sel < 2; ++sel) {
        const int* im = sel ? im2 : im1;
        const int* sh = sel ? sh2 : sh1;
        int* outp = sel ? &g_csel[b][0] : &g_rsel[b][0];

        int t0 = tid * 4;
        int v[4];
        int cnt = 0;
        #pragma unroll
        for (int i = 0; i < 4; ++i) {
            int t = t0 + i;
            v[i] = (im[b * T + t] != 0 && sh[b * T + t] != 0) ? 1 : 0;
            cnt += v[i];
        }
        int incl = cnt;
        #pragma unroll
        for (int o = 1; o < 32; o <<= 1) {
            int tt = __shfl_up_sync(0xffffffffu, incl, o);
            if (lane >= o) incl += tt;
        }
        if (lane == 31) wtot[wid] = incl;
        __syncthreads();
        if (wid == 0) {
            int val  = wtot[lane];
            int winc = val;
            #pragma unroll
            for (int o = 1; o < 32; o <<= 1) {
                int tt = __shfl_up_sync(0xffffffffu, winc, o);
                if (lane >= o) winc += tt;
            }
            wtot[lane] = winc - val;
            if (lane == 31) {
                if (sel) g_ny[b] = winc; else g_nx[b] = winc;
            }
        }
        __syncthreads();
        int off = wtot[wid] + (incl - cnt);
        #pragma unroll
        for (int i = 0; i < 4; ++i)
            if (v[i]) outp[off++] = t0 + i;
        __syncthreads();
    }
}

// ============================================================
// Kernel 2: gather selected rows + L2-normalize -> bf16 tiles
// ============================================================
__global__ void gather_norm_kernel(const float* __restrict__ x, const float* __restrict__ y) {
    int b     = blockIdx.y;
    int which = blockIdx.z;
    int wid  = threadIdx.x >> 5;
    int lane = threadIdx.x & 31;
    int p = blockIdx.x * 8 + wid;

    int count = which ? g_ny[b] : g_nx[b];
    if (p >= count) return;
    int r = which ? g_csel[b][p] : g_rsel[b][p];

    const float* src = (which ? y : x) + ((size_t)b * T + r) * D;
    float2 v = reinterpret_cast<const float2*>(src)[lane];
    float ss = v.x * v.x + v.y * v.y;
    #pragma unroll
    for (int o = 16; o > 0; o >>= 1) ss += __shfl_xor_sync(0xffffffffu, ss, o);
    float sc = 1.0f / fmaxf(sqrtf(ss), 1e-12f);

    __nv_bfloat16* dst = which ? &g_Yb[b][p][0] : &g_Xb[b][p][0];
    reinterpret_cast<__nv_bfloat162*>(dst)[lane] =
        __floats2bfloat162_rn(v.x * sc, v.y * sc);
}

// ============================================================
// Kernel 3: HMMA GEMM + fixed-shift column exp-sums + fused diag
// + per-CTA sum + fused last-CTA final combine.
// grid: (T/64, B) = 512 CTAs, block 256 (8 warps).
// TILE_COLS=64 -> ~48KB smem -> 2+ CTAs/SM: fills all 148 SMs and
// overlaps MUFU-exp with HMMA/LDSM across co-resident CTAs.
// ============================================================
constexpr int TILE_ROWS  = 128;
constexpr int TILE_COLS  = 64;
constexpr int SROW_BYTES = 144;          // 64 bf16 = 128B data + 16B pad
constexpr int GRID_X     = T / TILE_COLS;           // 64
constexpr unsigned TOTAL_CTAS = (unsigned)(GRID_X * B);  // 512

__global__ void __launch_bounds__(256, 2)
simloss_mma_kernel(float* __restrict__ out) {
    int b  = blockIdx.y;
    int nx = g_nx[b];
    int ny = g_ny[b];
    int m  = min(nx, ny);
    int colbase = blockIdx.x * TILE_COLS;

    int tid  = threadIdx.x;
    int lane = tid & 31;
    int w    = tid >> 5;               // warp 0..7

    __shared__ alignas(16) char sA[2][TILE_ROWS * SROW_BYTES];  // 2 x 18 KB
    __shared__ alignas(16) char sB[TILE_COLS * SROW_BYTES];     // 9 KB
    __shared__ float partial[8][TILE_COLS];                     // 2 KB
    __shared__ float redsum[8];
    __shared__ int   s_islast;
    __shared__ float sbatch[8];

    if (colbase < m) {
        // this thread's 4 A-staging slots (row, chunk)
        int srow[4], soff[4];
        #pragma unroll
        for (int i = 0; i < 4; ++i) {
            int g = i * 256 + tid;
            srow[i] = g >> 3;
            soff[i] = srow[i] * SROW_BYTES + (g & 7) * 16;
        }

        // stage B (Y rows colbase..colbase+63): 512 chunks, 2 per thread
        {
            const __nv_bfloat16* srcb = &g_Yb[b][colbase][0];
            #pragma unroll
            for (int i = 0; i < 2; ++i) {
                int g = i * 256 + tid;
                int row = g >> 3, chunk = g & 7;
                uint4 v = *reinterpret_cast<const uint4*>(srcb + row * D + chunk * 8);
                *reinterpret_cast<uint4*>(sB + row * SROW_BYTES + chunk * 16) = v;
            }
        }

        uint32_t sB_base = smem_u32(sB);
        uint32_t aOff = (uint32_t)((w * 16 + (lane & 15)) * SROW_BYTES
                                   + ((lane >> 4) & 1) * 16);
        uint32_t bAddr = sB_base + (uint32_t)((((lane & 7) + ((lane >> 4) & 1) * 8) * SROW_BYTES)
                                              + ((lane >> 3) & 1) * 16);

        float colacc[16];
        #pragma unroll
        for (int i = 0; i < 16; ++i) colacc[i] = 0.0f;

        int ntiles = (nx + TILE_ROWS - 1) / TILE_ROWS;

        // prologue: stage tile 0 into sA[0]
        {
            const __nv_bfloat16* src0 = &g_Xb[b][0][0];
            #pragma unroll
            for (int i = 0; i < 4; ++i) {
                int g = i * 256 + tid;
                uint4 v = *reinterpret_cast<const uint4*>(src0 + srow[i] * D + (g & 7) * 8);
                *reinterpret_cast<uint4*>(sA[0] + soff[i]) = v;
            }
        }
        __syncthreads();

        int cur = 0;
        for (int t = 0; t < ntiles; ++t) {
            // prefetch tile t+1 into registers (overlaps compute)
            uint4 pf[4];
            bool havenext = (t + 1 < ntiles);
            if (havenext) {
                const __nv_bfloat16* srcn = &g_Xb[b][(t + 1) * TILE_ROWS][0];
                #pragma unroll
                for (int i = 0; i < 4; ++i) {
                    int g = i * 256 + tid;
                    pf[i] = *reinterpret_cast<const uint4*>(srcn + srow[i] * D + (g & 7) * 8);
                }
            }

            uint32_t aAddr = smem_u32(sA[cur]) + aOff;
            uint32_t afr[4][4];
            #pragma unroll
            for (int ks = 0; ks < 4; ++ks)
                ldsm_x4(aAddr + ks * 32, afr[ks]);

            #pragma unroll
            for (int nt = 0; nt < 4; ++nt) {           // n16 tiles (64 cols)
                float c0[4] = {0.f, 0.f, 0.f, 0.f};
                float c1[4] = {0.f, 0.f, 0.f, 0.f};
                #pragma unroll
                for (int ks = 0; ks < 4; ++ks) {
                    uint32_t bfr[4];
                    ldsm_x4_trans(bAddr + nt * 16 * SROW_BYTES + ks * 32, bfr);
                    mma_bf16(c0, afr[ks], bfr[0], bfr[1]);   // n8 sub-tile 0
                    mma_bf16(c1, afr[ks], bfr[2], bfr[3]);   // n8 sub-tile 1
                }
                colacc[nt*4 + 0] += exp10s(c0[0]) + exp10s(c0[2]);
                colacc[nt*4 + 1] += exp10s(c0[1]) + exp10s(c0[3]);
                colacc[nt*4 + 2] += exp10s(c1[0]) + exp10s(c1[2]);
                colacc[nt*4 + 3] += exp10s(c1[1]) + exp10s(c1[3]);
            }

            if (havenext) {
                #pragma unroll
                for (int i = 0; i < 4; ++i)
                    *reinterpret_cast<uint4*>(sA[cur ^ 1] + soff[i]) = pf[i];
            }
            __syncthreads();
            cur ^= 1;
        }

        // reduce over the 8 row-owner lanes per column (validated mapping)
        #pragma unroll
        for (int e = 0; e < 16; ++e) {
            float v = colacc[e];
            v += __shfl_xor_sync(0xffffffffu, v, 4);
            v += __shfl_xor_sync(0xffffffffu, v, 8);
            v += __shfl_xor_sync(0xffffffffu, v, 16);
            if (lane < 4) {
                int nt = e >> 2, sub = (e >> 1) & 1, q = e & 1;
                partial[w][nt * 16 + sub * 8 + lane * 2 + q] = v;
            }
        }
        __syncthreads();

        // per-column term = lse - diag (fp32 diag from same bf16 values)
        float term = 0.0f;
        if (tid < TILE_COLS) {
            int c = colbase + tid;
            if (c < m) {
                float S = 0.0f;
                #pragma unroll
                for (int i = 0; i < 8; ++i) S += partial[i][tid];
                S -= (float)(ntiles * TILE_ROWS - nx) * __expf(-10.0f);

                float dsum = 0.0f;
                const uint4* xp = reinterpret_cast<const uint4*>(&g_Xb[b][c][0]);
                const uint4* yp = reinterpret_cast<const uint4*>(&g_Yb[b][c][0]);
                #pragma unroll
                for (int k = 0; k < 8; ++k) {
                    uint4 xv = xp[k], yv = yp[k];
                    const __nv_bfloat162* xh = reinterpret_cast<const __nv_bfloat162*>(&xv);
                    const __nv_bfloat162* yh = reinterpret_cast<const __nv_bfloat162*>(&yv);
                    #pragma unroll
                    for (int j = 0; j < 4; ++j) {
                        float2 xf = __bfloat1622float2(xh[j]);
                        float2 yf = __bfloat1622float2(yh[j]);
                        dsum += xf.x * yf.x + xf.y * yf.y;
                    }
                }
                term = 10.0f + logf(S) - 10.0f * dsum;
            }
        }
        #pragma unroll
        for (int o = 16; o > 0; o >>= 1) term += __shfl_xor_sync(0xffffffffu, term, o);
        if (lane == 0) redsum[w] = term;
        __syncthreads();
        if (tid == 0) {
            float s = 0.0f;
            #pragma unroll
            for (int i = 0; i < 8; ++i) s += redsum[i];
            g_tilesum[b][blockIdx.x] = s;
        }
    }

    // ---- last-CTA fused combine (every CTA arrives, incl. early-exit) ----
    if (tid == 0) {
        __threadfence();
        unsigned v = atomicAdd(&g_count, 1u);
        s_islast = (v == TOTAL_CTAS - 1u) ? 1 : 0;
        if (s_islast) g_count = 0;          // reset for next graph replay
    }
    __syncthreads();
    if (s_islast) {
        __threadfence();                    // order reads after all tilesum writes
        int mb  = min(g_nx[w], g_ny[w]);
        int ntc = (mb + TILE_COLS - 1) / TILE_COLS;   // <= 64 tiles
        float s = 0.0f;
        if (lane < ntc)      s += g_tilesum[w][lane];
        if (lane + 32 < ntc) s += g_tilesum[w][lane + 32];
        #pragma unroll
        for (int o = 16; o > 0; o >>= 1) s += __shfl_xor_sync(0xffffffffu, s, o);
        if (lane == 0) sbatch[w] = (mb > 0) ? s / (float)mb : 0.0f;
        __syncthreads();
        if (tid == 0) {
            float tsum = 0.0f;
            #pragma unroll
            for (int i = 0; i < 8; ++i) tsum += sbatch[i];
            out[0] = tsum / (float)B;
        }
    }
}

// ============================================================
extern "C" void kernel_launch(void* const* d_in, const int* in_sizes, int n_in,
                              void* d_out, int out_size) {
    const float* x   = (const float*)d_in[0];
    const float* y   = (const float*)d_in[1];
    const int*   im1 = (const int*)d_in[2];
    const int*   im2 = (const int*)d_in[3];
    const int*   sh1 = (const int*)d_in[4];
    const int*   sh2 = (const int*)d_in[5];

    compact_kernel<<<B, 1024>>>(im1, im2, sh1, sh2);
    gather_norm_kernel<<<dim3(T / 8, B, 2), 256>>>(x, y);
    simloss_mma_kernel<<<dim3(GRID_X, B), 256>>>((float*)d_out);
}